// round 3
// baseline (speedup 1.0000x reference)
#include <cuda_runtime.h>
#include <cuda_bf16.h>
#include <cstdint>

// Problem constants (match reference_code)
#define N_NODES   100000
#define IN_DIM    256
#define OUT_DIM   64
#define KEEP_INV  (1.0f / 0.9f)

// Scratch: h = dropout(x) @ W, [N_NODES, OUT_DIM] fp32 (25.6 MB, L2-resident)
__device__ __align__(16) float g_h[N_NODES * OUT_DIM];

// Vector reduction: one message carrying 4 floats (sm_90+), scalar fallback otherwise.
__device__ __forceinline__ void red_add_v4(float* dst, float4 c) {
#if __CUDA_ARCH__ >= 900
    asm volatile("red.global.add.v4.f32 [%0], {%1,%2,%3,%4};"
                 :: "l"(dst), "f"(c.x), "f"(c.y), "f"(c.z), "f"(c.w)
                 : "memory");
#else
    atomicAdd(dst + 0, c.x);
    atomicAdd(dst + 1, c.y);
    atomicAdd(dst + 2, c.z);
    atomicAdd(dst + 3, c.w);
#endif
}

// ---------------------------------------------------------------------------
// Zero scratch h and the output buffer (d_out is poisoned by the harness).
// ---------------------------------------------------------------------------
__global__ void zero_kernel(float* __restrict__ out, int n_out4) {
    int i = blockIdx.x * blockDim.x + threadIdx.x;
    const float4 z = make_float4(0.f, 0.f, 0.f, 0.f);
    const int h4 = (N_NODES * OUT_DIM) / 4;
    if (i < h4)     reinterpret_cast<float4*>(g_h)[i] = z;
    if (i < n_out4) reinterpret_cast<float4*>(out)[i] = z;
}

// ---------------------------------------------------------------------------
// SpMM1: h[row,:] += (keep ? xv*inv_keep : 0) * W[col,:]
// 16 threads per nnz, each owns 4 contiguous outputs -> one red.v4 each.
// keep_mask arrives as int32 (harness dtype set is {f32,i32,bf16}).
// ---------------------------------------------------------------------------
__global__ void spmm1_kernel(const float* __restrict__ x_vals,
                             const int*   __restrict__ x_rows,
                             const int*   __restrict__ x_cols,
                             const int*   __restrict__ keep,
                             const float* __restrict__ W,
                             int nnz) {
    long long tid = (long long)blockIdx.x * blockDim.x + threadIdx.x;
    int e = (int)(tid >> 4);
    if (e >= nnz) return;
    int q = (int)(tid & 15);

    if (keep[e] == 0) return;             // dropped entry: contributes nothing
    float v = x_vals[e] * KEEP_INV;

    int row = x_rows[e];
    int col = x_cols[e];
    float4 w = reinterpret_cast<const float4*>(W)[col * (OUT_DIM / 4) + q];
    float4 c = make_float4(w.x * v, w.y * v, w.z * v, w.w * v);

    red_add_v4(g_h + (long long)row * OUT_DIM + q * 4, c);
}

// ---------------------------------------------------------------------------
// SpMM2: out[row,:] += a * h[col,:]
// 16 threads per nnz, each gathers a float4 of h and fires one red.v4.
// ---------------------------------------------------------------------------
__global__ void spmm2_kernel(const float* __restrict__ adj_vals,
                             const int*   __restrict__ adj_rows,
                             const int*   __restrict__ adj_cols,
                             float* __restrict__ out,
                             int nnz) {
    long long tid = (long long)blockIdx.x * blockDim.x + threadIdx.x;
    int e = (int)(tid >> 4);
    if (e >= nnz) return;
    int q = (int)(tid & 15);

    float a  = adj_vals[e];
    int row  = adj_rows[e];
    int col  = adj_cols[e];

    float4 hv = reinterpret_cast<const float4*>(g_h)[(long long)col * (OUT_DIM / 4) + q];
    float4 c  = make_float4(hv.x * a, hv.y * a, hv.z * a, hv.w * a);

    red_add_v4(out + (long long)row * OUT_DIM + q * 4, c);
}

// ---------------------------------------------------------------------------
// ReLU in place on the output.
// ---------------------------------------------------------------------------
__global__ void relu_kernel(float* __restrict__ out, int n4) {
    int i = blockIdx.x * blockDim.x + threadIdx.x;
    if (i >= n4) return;
    float4 v = reinterpret_cast<float4*>(out)[i];
    v.x = fmaxf(v.x, 0.f);
    v.y = fmaxf(v.y, 0.f);
    v.z = fmaxf(v.z, 0.f);
    v.w = fmaxf(v.w, 0.f);
    reinterpret_cast<float4*>(out)[i] = v;
}

// ---------------------------------------------------------------------------
// Input order (reference setup_inputs):
//  0 x_vals f32[1.6M], 1 x_rows i32, 2 x_cols i32,
//  3 adj_vals f32[3.2M], 4 adj_rows i32, 5 adj_cols i32,
//  6 W f32[256*64], 7 keep_mask (bool -> int32)
// ---------------------------------------------------------------------------
extern "C" void kernel_launch(void* const* d_in, const int* in_sizes, int n_in,
                              void* d_out, int out_size) {
    if (n_in < 8) return;

    const float* x_vals   = (const float*)d_in[0];
    const int*   x_rows   = (const int*)  d_in[1];
    const int*   x_cols   = (const int*)  d_in[2];
    const float* adj_vals = (const float*)d_in[3];
    const int*   adj_rows = (const int*)  d_in[4];
    const int*   adj_cols = (const int*)  d_in[5];
    const float* W        = (const float*)d_in[6];
    const int*   keep     = (const int*)  d_in[7];

    const int x_nnz = in_sizes[0];
    const int a_nnz = in_sizes[3];
    float* out = (float*)d_out;

    const int threads = 256;

    // zero h + out
    {
        int h4 = (N_NODES * OUT_DIM) / 4;
        int o4 = out_size / 4;
        int n  = h4 > o4 ? h4 : o4;
        zero_kernel<<<(n + threads - 1) / threads, threads>>>(out, o4);
    }

    // spmm1: 16 threads per nnz
    {
        long long total = (long long)x_nnz * 16;
        int blocks = (int)((total + threads - 1) / threads);
        if (blocks > 0)
            spmm1_kernel<<<blocks, threads>>>(x_vals, x_rows, x_cols, keep, W, x_nnz);
    }

    // spmm2: 16 threads per nnz
    {
        long long total = (long long)a_nnz * 16;
        int blocks = (int)((total + threads - 1) / threads);
        if (blocks > 0)
            spmm2_kernel<<<blocks, threads>>>(adj_vals, adj_rows, adj_cols, out, a_nnz);
    }

    // relu
    {
        int o4 = out_size / 4;
        if (o4 > 0)
            relu_kernel<<<(o4 + threads - 1) / threads, threads>>>(out, o4);
    }
}

// round 4
// speedup vs baseline: 1.3099x; 1.3099x over previous
#include <cuda_runtime.h>
#include <cuda_bf16.h>
#include <cstdint>

// Problem constants (match reference_code)
#define N_NODES   100000
#define IN_DIM    256
#define OUT_DIM   64
#define X_CAP     1600000
#define A_CAP     3200000
#define KEEP_INV  (1.0f / 0.9f)
#define NBLK      ((N_NODES + 255) / 256)   // 391

// ---------------------------------------------------------------------------
// Scratch (static device globals; no runtime allocation).
// ---------------------------------------------------------------------------
__device__ __align__(16) float g_h[N_NODES * OUT_DIM];   // 25.6 MB
__device__ int   g_xcnt[N_NODES], g_acnt[N_NODES];
__device__ int   g_xoff[N_NODES], g_aoff[N_NODES];
__device__ int   g_xcur[N_NODES], g_acur[N_NODES];
__device__ int   g_partx[NBLK],   g_parta[NBLK];
__device__ int   g_pxcol[X_CAP];  __device__ float g_pxval[X_CAP];
__device__ int   g_pacol[A_CAP];  __device__ float g_paval[A_CAP];

// ---------------------------------------------------------------------------
// 1) Zero the per-row counters.
// ---------------------------------------------------------------------------
__global__ void zero_cnt_kernel() {
    int i = blockIdx.x * blockDim.x + threadIdx.x;
    if (i < N_NODES) { g_xcnt[i] = 0; g_acnt[i] = 0; }
}

// ---------------------------------------------------------------------------
// 2) Histogram rows (x filtered by keep_mask; dropped entries vanish here).
// ---------------------------------------------------------------------------
__global__ void hist_kernel(const int* __restrict__ x_rows,
                            const int* __restrict__ keep, int xnnz,
                            const int* __restrict__ adj_rows, int annz) {
    int i = blockIdx.x * blockDim.x + threadIdx.x;
    if (i < xnnz && keep[i] != 0) atomicAdd(&g_xcnt[x_rows[i]], 1);
    if (i < annz)                 atomicAdd(&g_acnt[adj_rows[i]], 1);
}

// ---------------------------------------------------------------------------
// 3) Per-block partial sums of the count arrays.
// ---------------------------------------------------------------------------
__global__ void partial_kernel() {
    __shared__ int shx[256], sha[256];
    int t = threadIdx.x;
    int i = blockIdx.x * 256 + t;
    shx[t] = (i < N_NODES) ? g_xcnt[i] : 0;
    sha[t] = (i < N_NODES) ? g_acnt[i] : 0;
    __syncthreads();
    for (int d = 128; d > 0; d >>= 1) {
        if (t < d) { shx[t] += shx[t + d]; sha[t] += sha[t + d]; }
        __syncthreads();
    }
    if (t == 0) { g_partx[blockIdx.x] = shx[0]; g_parta[blockIdx.x] = sha[0]; }
}

// ---------------------------------------------------------------------------
// 4) Exclusive scan of the partials (warp 0: x, warp 1: adj). NBLK = 391.
// ---------------------------------------------------------------------------
__global__ void scan_partials_kernel() {
    int w    = threadIdx.x >> 5;
    int lane = threadIdx.x & 31;
    if (w > 1) return;
    int* p = (w == 0) ? g_partx : g_parta;
    int carry = 0;
    for (int base = 0; base < NBLK; base += 32) {
        int idx = base + lane;
        int v   = (idx < NBLK) ? p[idx] : 0;
        int orig = v;
        #pragma unroll
        for (int d = 1; d < 32; d <<= 1) {
            int t = __shfl_up_sync(0xffffffffu, v, d);
            if (lane >= d) v += t;
        }
        if (idx < NBLK) p[idx] = carry + v - orig;   // exclusive
        carry += __shfl_sync(0xffffffffu, v, 31);
    }
}

// ---------------------------------------------------------------------------
// 5) Per-element offsets: block-local exclusive scan + scanned partial.
//    Writes both the row-start array and the scatter cursor copy.
// ---------------------------------------------------------------------------
__global__ void offsets_kernel() {
    __shared__ int sh[256];
    int t = threadIdx.x;
    int i = blockIdx.x * 256 + t;

    // --- x ---
    int vx = (i < N_NODES) ? g_xcnt[i] : 0;
    sh[t] = vx; __syncthreads();
    for (int d = 1; d < 256; d <<= 1) {
        int add = (t >= d) ? sh[t - d] : 0;
        __syncthreads();
        sh[t] += add;
        __syncthreads();
    }
    if (i < N_NODES) {
        int off = g_partx[blockIdx.x] + sh[t] - vx;
        g_xoff[i] = off; g_xcur[i] = off;
    }
    __syncthreads();

    // --- adj ---
    int va = (i < N_NODES) ? g_acnt[i] : 0;
    sh[t] = va; __syncthreads();
    for (int d = 1; d < 256; d <<= 1) {
        int add = (t >= d) ? sh[t - d] : 0;
        __syncthreads();
        sh[t] += add;
        __syncthreads();
    }
    if (i < N_NODES) {
        int off = g_parta[blockIdx.x] + sh[t] - va;
        g_aoff[i] = off; g_acur[i] = off;
    }
}

// ---------------------------------------------------------------------------
// 6) Scatter entries into row-grouped arrays (dropout applied to x here).
// ---------------------------------------------------------------------------
__global__ void scatter_kernel(const float* __restrict__ x_vals,
                               const int*   __restrict__ x_rows,
                               const int*   __restrict__ x_cols,
                               const int*   __restrict__ keep, int xnnz,
                               const float* __restrict__ adj_vals,
                               const int*   __restrict__ adj_rows,
                               const int*   __restrict__ adj_cols, int annz) {
    int i = blockIdx.x * blockDim.x + threadIdx.x;
    if (i < xnnz && keep[i] != 0) {
        int s = atomicAdd(&g_xcur[x_rows[i]], 1);
        g_pxcol[s] = x_cols[i];
        g_pxval[s] = x_vals[i] * KEEP_INV;
    }
    if (i < annz) {
        int s = atomicAdd(&g_acur[adj_rows[i]], 1);
        g_pacol[s] = adj_cols[i];
        g_paval[s] = adj_vals[i];
    }
}

// ---------------------------------------------------------------------------
// 7) SpMM1 (CSR gather): one warp per node; thread t owns outputs t, t+32.
//    h[n,:] = sum_e v_e * W[col_e,:]   (W is L1-resident, 64 KB)
// ---------------------------------------------------------------------------
__global__ void spmm1_csr_kernel(const float* __restrict__ W) {
    int warp = (blockIdx.x * blockDim.x + threadIdx.x) >> 5;
    int lane = threadIdx.x & 31;
    if (warp >= N_NODES) return;

    int s = g_xoff[warp];
    int c = g_xcnt[warp];
    float a0 = 0.f, a1 = 0.f;

    for (int base = 0; base < c; base += 32) {
        int idx = base + lane;
        int col = 0; float v = 0.f;
        if (idx < c) { col = g_pxcol[s + idx]; v = g_pxval[s + idx]; }
        int m = min(32, c - base);
        if (m == 32) {
            #pragma unroll 8
            for (int j = 0; j < 32; ++j) {
                int   cj = __shfl_sync(0xffffffffu, col, j);
                float vj = __shfl_sync(0xffffffffu, v,   j);
                a0 = fmaf(vj, W[cj * OUT_DIM + lane],      a0);
                a1 = fmaf(vj, W[cj * OUT_DIM + 32 + lane], a1);
            }
        } else {
            for (int j = 0; j < m; ++j) {
                int   cj = __shfl_sync(0xffffffffu, col, j);
                float vj = __shfl_sync(0xffffffffu, v,   j);
                a0 = fmaf(vj, W[cj * OUT_DIM + lane],      a0);
                a1 = fmaf(vj, W[cj * OUT_DIM + 32 + lane], a1);
            }
        }
    }
    g_h[warp * OUT_DIM + lane]      = a0;
    g_h[warp * OUT_DIM + 32 + lane] = a1;
}

// ---------------------------------------------------------------------------
// 8) SpMM2 (CSR gather) + fused ReLU: one warp per node.
//    out[n,:] = relu( sum_e a_e * h[col_e,:] )  (h is L2-resident, 25.6 MB)
// ---------------------------------------------------------------------------
__global__ void spmm2_csr_kernel(float* __restrict__ out) {
    int warp = (blockIdx.x * blockDim.x + threadIdx.x) >> 5;
    int lane = threadIdx.x & 31;
    if (warp >= N_NODES) return;

    int s = g_aoff[warp];
    int c = g_acnt[warp];
    float a0 = 0.f, a1 = 0.f;

    for (int base = 0; base < c; base += 32) {
        int idx = base + lane;
        int col = 0; float v = 0.f;
        if (idx < c) { col = g_pacol[s + idx]; v = g_paval[s + idx]; }
        int m = min(32, c - base);
        if (m == 32) {
            #pragma unroll 8
            for (int j = 0; j < 32; ++j) {
                int   cj = __shfl_sync(0xffffffffu, col, j);
                float vj = __shfl_sync(0xffffffffu, v,   j);
                a0 = fmaf(vj, g_h[cj * OUT_DIM + lane],      a0);
                a1 = fmaf(vj, g_h[cj * OUT_DIM + 32 + lane], a1);
            }
        } else {
            for (int j = 0; j < m; ++j) {
                int   cj = __shfl_sync(0xffffffffu, col, j);
                float vj = __shfl_sync(0xffffffffu, v,   j);
                a0 = fmaf(vj, g_h[cj * OUT_DIM + lane],      a0);
                a1 = fmaf(vj, g_h[cj * OUT_DIM + 32 + lane], a1);
            }
        }
    }
    out[warp * OUT_DIM + lane]      = fmaxf(a0, 0.f);
    out[warp * OUT_DIM + 32 + lane] = fmaxf(a1, 0.f);
}

// ---------------------------------------------------------------------------
// Input order: 0 x_vals, 1 x_rows, 2 x_cols, 3 adj_vals, 4 adj_rows,
//              5 adj_cols, 6 W, 7 keep_mask(int32)
// ---------------------------------------------------------------------------
extern "C" void kernel_launch(void* const* d_in, const int* in_sizes, int n_in,
                              void* d_out, int out_size) {
    if (n_in < 8) return;

    const float* x_vals   = (const float*)d_in[0];
    const int*   x_rows   = (const int*)  d_in[1];
    const int*   x_cols   = (const int*)  d_in[2];
    const float* adj_vals = (const float*)d_in[3];
    const int*   adj_rows = (const int*)  d_in[4];
    const int*   adj_cols = (const int*)  d_in[5];
    const float* W        = (const float*)d_in[6];
    const int*   keep     = (const int*)  d_in[7];

    int x_nnz = in_sizes[0]; if (x_nnz > X_CAP) x_nnz = X_CAP;
    int a_nnz = in_sizes[3]; if (a_nnz > A_CAP) a_nnz = A_CAP;
    float* out = (float*)d_out;

    const int T = 256;
    int nmax = (x_nnz > a_nnz) ? x_nnz : a_nnz;

    // CSR build
    zero_cnt_kernel<<<NBLK, T>>>();
    hist_kernel<<<(nmax + T - 1) / T, T>>>(x_rows, keep, x_nnz, adj_rows, a_nnz);
    partial_kernel<<<NBLK, T>>>();
    scan_partials_kernel<<<1, 64>>>();
    offsets_kernel<<<NBLK, T>>>();
    scatter_kernel<<<(nmax + T - 1) / T, T>>>(x_vals, x_rows, x_cols, keep, x_nnz,
                                              adj_vals, adj_rows, adj_cols, a_nnz);

    // Gather-reduce SpMMs (one warp per node; 8 warps per block)
    int warp_blocks = (N_NODES * 32 + T - 1) / T;
    spmm1_csr_kernel<<<warp_blocks, T>>>(W);
    spmm2_csr_kernel<<<warp_blocks, T>>>(out);
}

// round 5
// speedup vs baseline: 1.5632x; 1.1934x over previous
#include <cuda_runtime.h>
#include <cuda_bf16.h>
#include <cstdint>

// Problem constants (match reference_code)
#define N_NODES   100000
#define IN_DIM    256
#define OUT_DIM   64
#define X_CAP     1600000
#define A_CAP     3200000
#define KEEP_INV  (1.0f / 0.9f)
#define NBLK      ((N_NODES + 255) / 256)   // 391

// ---------------------------------------------------------------------------
// Scratch (static device globals; no runtime allocation).
// ---------------------------------------------------------------------------
__device__ __align__(16) float g_h[N_NODES * OUT_DIM];   // 25.6 MB
__device__ int  g_xcnt[N_NODES], g_acnt[N_NODES];
__device__ int  g_xoff[N_NODES], g_aoff[N_NODES];
__device__ int  g_xcur[N_NODES], g_acur[N_NODES];
__device__ int  g_xtot, g_atot;
__device__ __align__(16) int2 g_pax[X_CAP];   // (col, bits(val))  row-grouped x
__device__ __align__(16) int2 g_paa[A_CAP];   // (col, bits(val))  row-grouped adj

// ---------------------------------------------------------------------------
// 1) Zero per-row counters + global cursors.
// ---------------------------------------------------------------------------
__global__ void zero_cnt_kernel() {
    int i = blockIdx.x * blockDim.x + threadIdx.x;
    if (i < N_NODES) { g_xcnt[i] = 0; g_acnt[i] = 0; }
    if (i == 0) { g_xtot = 0; g_atot = 0; }
}

// ---------------------------------------------------------------------------
// 2) Histogram rows (x filtered by keep_mask; dropped entries vanish here).
// ---------------------------------------------------------------------------
__global__ void hist_kernel(const int* __restrict__ x_rows,
                            const int* __restrict__ keep, int xnnz,
                            const int* __restrict__ adj_rows, int annz) {
    int i = blockIdx.x * blockDim.x + threadIdx.x;
    if (i < xnnz && keep[i] != 0) atomicAdd(&g_xcnt[x_rows[i]], 1);
    if (i < annz)                 atomicAdd(&g_acnt[adj_rows[i]], 1);
}

// ---------------------------------------------------------------------------
// 3) Row offsets WITHOUT a global scan: segment order is irrelevant, so each
//    warp claims space for its 32 rows via one atomicAdd on a global cursor
//    and distributes it with a warp-local exclusive scan.
// ---------------------------------------------------------------------------
__global__ void offsets_kernel() {
    int i    = blockIdx.x * blockDim.x + threadIdx.x;
    int lane = threadIdx.x & 31;

    int cx = (i < N_NODES) ? g_xcnt[i] : 0;
    int ca = (i < N_NODES) ? g_acnt[i] : 0;

    int sx = cx, sa = ca;                       // inclusive scans
    #pragma unroll
    for (int d = 1; d < 32; d <<= 1) {
        int tx = __shfl_up_sync(0xffffffffu, sx, d);
        int ta = __shfl_up_sync(0xffffffffu, sa, d);
        if (lane >= d) { sx += tx; sa += ta; }
    }

    int basex = 0, basea = 0;
    if (lane == 31) {
        basex = atomicAdd(&g_xtot, sx);         // sx at lane 31 == warp total
        basea = atomicAdd(&g_atot, sa);
    }
    basex = __shfl_sync(0xffffffffu, basex, 31);
    basea = __shfl_sync(0xffffffffu, basea, 31);

    if (i < N_NODES) {
        int ox = basex + sx - cx;               // exclusive position
        int oa = basea + sa - ca;
        g_xoff[i] = ox; g_xcur[i] = ox;
        g_aoff[i] = oa; g_acur[i] = oa;
    }
}

// ---------------------------------------------------------------------------
// 4) Scatter entries into row-grouped (col,val) pairs; dropout applied here.
// ---------------------------------------------------------------------------
__global__ void scatter_kernel(const float* __restrict__ x_vals,
                               const int*   __restrict__ x_rows,
                               const int*   __restrict__ x_cols,
                               const int*   __restrict__ keep, int xnnz,
                               const float* __restrict__ adj_vals,
                               const int*   __restrict__ adj_rows,
                               const int*   __restrict__ adj_cols, int annz) {
    int i = blockIdx.x * blockDim.x + threadIdx.x;
    if (i < xnnz && keep[i] != 0) {
        int s = atomicAdd(&g_xcur[x_rows[i]], 1);
        g_pax[s] = make_int2(x_cols[i], __float_as_int(x_vals[i] * KEEP_INV));
    }
    if (i < annz) {
        int s = atomicAdd(&g_acur[adj_rows[i]], 1);
        g_paa[s] = make_int2(adj_cols[i], __float_as_int(adj_vals[i]));
    }
}

// ---------------------------------------------------------------------------
// 5) SpMM1 (CSR gather): one warp per node; lane t owns outputs [2t, 2t+1].
//    h[n,:] = sum_e v_e * W[col_e,:]   (W 64 KB, L1-resident; float2 loads)
// ---------------------------------------------------------------------------
__global__ void spmm1_csr_kernel(const float* __restrict__ W) {
    int warp = (blockIdx.x * blockDim.x + threadIdx.x) >> 5;
    int lane = threadIdx.x & 31;
    if (warp >= N_NODES) return;

    const float2* __restrict__ W2 = (const float2*)W;
    int s = g_xoff[warp];
    int c = g_xcnt[warp];
    float2 acc = make_float2(0.f, 0.f);

    for (int base = 0; base < c; base += 32) {
        int idx = base + lane;
        int2 e = (idx < c) ? g_pax[s + idx] : make_int2(0, 0);
        int m = min(32, c - base);
        if (m == 32) {
            #pragma unroll 8
            for (int j = 0; j < 32; ++j) {
                int   cj = __shfl_sync(0xffffffffu, e.x, j);
                float vj = __int_as_float(__shfl_sync(0xffffffffu, e.y, j));
                float2 w = W2[cj * (OUT_DIM / 2) + lane];
                acc.x = fmaf(vj, w.x, acc.x);
                acc.y = fmaf(vj, w.y, acc.y);
            }
        } else {
            for (int j = 0; j < m; ++j) {
                int   cj = __shfl_sync(0xffffffffu, e.x, j);
                float vj = __int_as_float(__shfl_sync(0xffffffffu, e.y, j));
                float2 w = W2[cj * (OUT_DIM / 2) + lane];
                acc.x = fmaf(vj, w.x, acc.x);
                acc.y = fmaf(vj, w.y, acc.y);
            }
        }
    }
    reinterpret_cast<float2*>(g_h)[warp * (OUT_DIM / 2) + lane] = acc;
}

// ---------------------------------------------------------------------------
// 6) SpMM2 (CSR gather) + fused ReLU: one warp per node.
//    out[n,:] = relu( sum_e a_e * h[col_e,:] )  (h 25.6 MB, L2-resident)
// ---------------------------------------------------------------------------
__global__ void spmm2_csr_kernel(float* __restrict__ out) {
    int warp = (blockIdx.x * blockDim.x + threadIdx.x) >> 5;
    int lane = threadIdx.x & 31;
    if (warp >= N_NODES) return;

    const float2* __restrict__ h2 = (const float2*)g_h;
    int s = g_aoff[warp];
    int c = g_acnt[warp];
    float2 acc = make_float2(0.f, 0.f);

    for (int base = 0; base < c; base += 32) {
        int idx = base + lane;
        int2 e = (idx < c) ? g_paa[s + idx] : make_int2(0, 0);
        int m = min(32, c - base);
        if (m == 32) {
            #pragma unroll 8
            for (int j = 0; j < 32; ++j) {
                int   cj = __shfl_sync(0xffffffffu, e.x, j);
                float vj = __int_as_float(__shfl_sync(0xffffffffu, e.y, j));
                float2 hv = h2[cj * (OUT_DIM / 2) + lane];
                acc.x = fmaf(vj, hv.x, acc.x);
                acc.y = fmaf(vj, hv.y, acc.y);
            }
        } else {
            for (int j = 0; j < m; ++j) {
                int   cj = __shfl_sync(0xffffffffu, e.x, j);
                float vj = __int_as_float(__shfl_sync(0xffffffffu, e.y, j));
                float2 hv = h2[cj * (OUT_DIM / 2) + lane];
                acc.x = fmaf(vj, hv.x, acc.x);
                acc.y = fmaf(vj, hv.y, acc.y);
            }
        }
    }
    acc.x = fmaxf(acc.x, 0.f);
    acc.y = fmaxf(acc.y, 0.f);
    reinterpret_cast<float2*>(out)[warp * (OUT_DIM / 2) + lane] = acc;
}

// ---------------------------------------------------------------------------
// Input order: 0 x_vals, 1 x_rows, 2 x_cols, 3 adj_vals, 4 adj_rows,
//              5 adj_cols, 6 W, 7 keep_mask(int32)
// ---------------------------------------------------------------------------
extern "C" void kernel_launch(void* const* d_in, const int* in_sizes, int n_in,
                              void* d_out, int out_size) {
    if (n_in < 8) return;

    const float* x_vals   = (const float*)d_in[0];
    const int*   x_rows   = (const int*)  d_in[1];
    const int*   x_cols   = (const int*)  d_in[2];
    const float* adj_vals = (const float*)d_in[3];
    const int*   adj_rows = (const int*)  d_in[4];
    const int*   adj_cols = (const int*)  d_in[5];
    const float* W        = (const float*)d_in[6];
    const int*   keep     = (const int*)  d_in[7];

    int x_nnz = in_sizes[0]; if (x_nnz > X_CAP) x_nnz = X_CAP;
    int a_nnz = in_sizes[3]; if (a_nnz > A_CAP) a_nnz = A_CAP;
    float* out = (float*)d_out;

    const int T = 256;
    int nmax = (x_nnz > a_nnz) ? x_nnz : a_nnz;

    // CSR build (segment order irrelevant -> no global scan)
    zero_cnt_kernel<<<NBLK, T>>>();
    hist_kernel<<<(nmax + T - 1) / T, T>>>(x_rows, keep, x_nnz, adj_rows, a_nnz);
    offsets_kernel<<<NBLK, T>>>();
    scatter_kernel<<<(nmax + T - 1) / T, T>>>(x_vals, x_rows, x_cols, keep, x_nnz,
                                              adj_vals, adj_rows, adj_cols, a_nnz);

    // Gather-reduce SpMMs (one warp per node; 8 warps per block)
    int warp_blocks = (N_NODES * 32 + T - 1) / T;
    spmm1_csr_kernel<<<warp_blocks, T>>>(W);
    spmm2_csr_kernel<<<warp_blocks, T>>>(out);
}